// round 14
// baseline (speedup 1.0000x reference)
#include <cuda_runtime.h>
#include <math.h>

#define HH 512
#define WW 512
#define HW (HH*WW)
#define NCH_IN 48
#define NCH_OUT 21
#define MAXB 8

// Streams/events for forked-capture overlap; created at program load,
// before the harness's first memory checkpoint. No device allocations here.
static cudaStream_t g_s1;
static cudaEvent_t  g_evMain[MAXB];
static cudaEvent_t  g_evJoin;
namespace {
struct GInit {
    GInit() {
        cudaStreamCreateWithFlags(&g_s1, cudaStreamNonBlocking);
        for (int i = 0; i < MAXB; ++i)
            cudaEventCreateWithFlags(&g_evMain[i], cudaEventDisableTiming);
        cudaEventCreateWithFlags(&g_evJoin, cudaEventDisableTiming);
    }
};
static GInit g_init;
}

// Adjugate (unscaled inverse) via 2x2-minor decomposition; returns det.
__device__ __forceinline__ float adj4(const float* m, float* o) {
    float s0 = m[0]*m[5]  - m[4]*m[1];
    float s1 = m[0]*m[6]  - m[4]*m[2];
    float s2 = m[0]*m[7]  - m[4]*m[3];
    float s3 = m[1]*m[6]  - m[5]*m[2];
    float s4 = m[1]*m[7]  - m[5]*m[3];
    float s5 = m[2]*m[7]  - m[6]*m[3];
    float c5 = m[10]*m[15] - m[14]*m[11];
    float c4 = m[9]*m[15]  - m[13]*m[11];
    float c3 = m[9]*m[14]  - m[13]*m[10];
    float c2 = m[8]*m[15]  - m[12]*m[11];
    float c1 = m[8]*m[14]  - m[12]*m[10];
    float c0 = m[8]*m[13]  - m[12]*m[9];
    float det = s0*c5 - s1*c4 + s2*c3 + s3*c2 - s4*c1 + s5*c0;
    o[0]  =  m[5]*c5 - m[6]*c4 + m[7]*c3;
    o[1]  = -m[1]*c5 + m[2]*c4 - m[3]*c3;
    o[2]  =  m[13]*s5 - m[14]*s4 + m[15]*s3;
    o[3]  = -m[9]*s5  + m[10]*s4 - m[11]*s3;
    o[4]  = -m[4]*c5 + m[6]*c2 - m[7]*c1;
    o[5]  =  m[0]*c5 - m[2]*c2 + m[3]*c1;
    o[6]  = -m[12]*s5 + m[14]*s2 - m[15]*s1;
    o[7]  =  m[8]*s5  - m[10]*s2 + m[11]*s1;
    o[8]  =  m[4]*c4 - m[5]*c2 + m[7]*c0;
    o[9]  = -m[0]*c4 + m[1]*c2 - m[3]*c0;
    o[10] =  m[12]*s4 - m[13]*s2 + m[15]*s0;
    o[11] = -m[8]*s4  + m[9]*s2  - m[11]*s0;
    o[12] = -m[4]*c3 + m[5]*c1 - m[6]*c0;
    o[13] =  m[0]*c3 - m[1]*c1 + m[2]*c0;
    o[14] = -m[12]*s3 + m[13]*s1 - m[14]*s0;
    o[15] =  m[8]*s3  - m[9]*s1  + m[10]*s0;
    return det;
}

__device__ __forceinline__ void mat4mul(const float* a, const float* b, float* o) {
#pragma unroll
    for (int i = 0; i < 4; ++i)
#pragma unroll
        for (int j = 0; j < 4; ++j)
            o[i*4+j] = a[i*4+0]*b[j] + a[i*4+1]*b[4+j] + a[i*4+2]*b[8+j] + a[i*4+3]*b[12+j];
}

__device__ __forceinline__ float det3v(const float g[9]) {
    return g[0]*(g[4]*g[8]-g[5]*g[7]) - g[1]*(g[3]*g[8]-g[5]*g[6]) + g[2]*(g[3]*g[7]-g[4]*g[6]);
}

// inv3x3 with caller-provided numerator (scale folded into reciprocal)
__device__ __forceinline__ void inv3x3s(const float g[9], float num, float o[9]) {
    float c00 = g[4]*g[8]-g[5]*g[7];
    float c01 = g[2]*g[7]-g[1]*g[8];
    float c02 = g[1]*g[5]-g[2]*g[4];
    float c10 = g[5]*g[6]-g[3]*g[8];
    float c11 = g[0]*g[8]-g[2]*g[6];
    float c12 = g[2]*g[3]-g[0]*g[5];
    float c20 = g[3]*g[7]-g[4]*g[6];
    float c21 = g[1]*g[6]-g[0]*g[7];
    float c22 = g[0]*g[4]-g[1]*g[3];
    float det = g[0]*c00 + g[1]*c10 + g[2]*c20;
    float rd = __fdividef(num, det);
    o[0]=c00*rd; o[1]=c01*rd; o[2]=c02*rd;
    o[3]=c10*rd; o[4]=c11*rd; o[5]=c12*rd;
    o[6]=c20*rd; o[7]=c21*rd; o[8]=c22*rd;
}

#define DEG 57.29577951308232f

// One batch per launch (bb passed in) so mm_std(b) can overlap mm_main(b+1).
__global__ void __launch_bounds__(128, 4) mm_main(const float* __restrict__ x,
                                                  float* __restrict__ out, int bb) {
    int pix = blockIdx.x*blockDim.x + threadIdx.x;
    if (pix >= HW) return;
    const float* px = x + (size_t)bb*(NCH_IN*HW) + pix;

    // --- stage 1: A -> adjA, detA (A dies immediately) ---
    float adjA[16];
    float detA;
    {
        float Aa[16];
#pragma unroll
        for (int c = 0; c < 16; ++c) Aa[c] = __ldcs(px + (16+c)*HW);
        detA = adj4(Aa, adjA);
    }

    // --- stage 2: I -> intensity, Tm = adjA @ I (I, adjA die) ---
    float Tm[16];
    float inten = 0.f;
    {
        float Im[16];
#pragma unroll
        for (int c = 0; c < 16; ++c) Im[c] = __ldcs(px + c*HW);
#pragma unroll
        for (int c = 0; c < 16; ++c) inten += Im[c];
        inten *= (1.0f/16.0f);
        mat4mul(adjA, Im, Tm);
    }

    // --- stage 3: W -> adjW, M = (Tm @ adjW) / (detA*detW) ---
    float M[16];
    {
        float Wm[16];
#pragma unroll
        for (int c = 0; c < 16; ++c) Wm[c] = __ldcs(px + (32+c)*HW);
        float adjW[16];
        float detW = adj4(Wm, adjW);
        mat4mul(Tm, adjW, M);
        float sc = __fdividef(1.0f, detA*detW);
#pragma unroll
        for (int c = 0; c < 16; ++c) M[c] *= sc;
    }

    float* po = out + (size_t)bb*(NCH_OUT*HW) + pix;
    __stcs(po, inten);
#pragma unroll
    for (int c = 0; c < 16; ++c) __stcs(po + (1+c)*HW, M[c]);

    // ---- charpoly (physical realizability) mask via coherency matrix H ----
    const float q = 0.25f;
    float h00 = q*((M[0]+M[1]) + (M[4]+M[5]));
    float h11 = q*((M[0]-M[1]) + (M[4]-M[5]));
    float h22 = q*((M[0]+M[1]) - (M[4]+M[5]));
    float h33 = q*((M[0]-M[1]) - (M[4]-M[5]));
    float a01r = q*(M[2]+M[6]),   a01i =  q*(M[3]+M[7]);
    float a23r = q*(M[2]-M[6]),   a23i =  q*(M[3]-M[7]);
    float a02r = q*(M[8]+M[9]),   a02i = -q*(M[12]+M[13]);
    float a13r = q*(M[8]-M[9]),   a13i = -q*(M[12]-M[13]);
    float a03r = q*(M[10]+M[15]), a03i =  q*(M[11]-M[14]);
    float a12r = q*(M[10]-M[15]), a12i = -q*(M[11]+M[14]);

    float n01 = a01r*a01r + a01i*a01i;
    float n02 = a02r*a02r + a02i*a02i;
    float n03 = a03r*a03r + a03i*a03i;
    float n12 = a12r*a12r + a12i*a12i;
    float n13 = a13r*a13r + a13i*a13i;
    float n23 = a23r*a23r + a23i*a23i;

    float p1 = h00+h11+h22+h33;
    float p2 = h00*h00+h11*h11+h22*h22+h33*h33 + 2.f*(n01+n02+n03+n12+n13+n23);

    float g00 = h00*h00 + n01+n02+n03;
    float g11 = h11*h11 + n01+n12+n13;
    float g22 = h22*h22 + n02+n12+n23;
    float g33 = h33*h33 + n03+n13+n23;

    float s01 = h00+h11, s02=h00+h22, s03=h00+h33, s12=h11+h22, s13=h11+h33, s23=h22+h33;
    float b01r = s01*a01r + (a02r*a12r + a02i*a12i) + (a03r*a13r + a03i*a13i);
    float b01i = s01*a01i + (a02i*a12r - a02r*a12i) + (a03i*a13r - a03r*a13i);
    float b02r = s02*a02r + (a01r*a12r - a01i*a12i) + (a03r*a23r + a03i*a23i);
    float b02i = s02*a02i + (a01r*a12i + a01i*a12r) + (a03i*a23r - a03r*a23i);
    float b03r = s03*a03r + (a01r*a13r - a01i*a13i) + (a02r*a23r - a02i*a23i);
    float b03i = s03*a03i + (a01r*a13i + a01i*a13r) + (a02r*a23i + a02i*a23r);
    float b12r = s12*a12r + (a01r*a02r + a01i*a02i) + (a13r*a23r + a13i*a23i);
    float b12i = s12*a12i + (a01r*a02i - a01i*a02r) + (a13i*a23r - a13r*a23i);
    float b13r = s13*a13r + (a01r*a03r + a01i*a03i) + (a12r*a23r - a12i*a23i);
    float b13i = s13*a13i + (a01r*a03i - a01i*a03r) + (a12r*a23i + a12i*a23r);
    float b23r = s23*a23r + (a02r*a03r + a02i*a03i) + (a12r*a13r + a12i*a13i);
    float b23i = s23*a23i + (a02r*a03i - a02i*a03r) + (a12r*a13i - a12i*a13r);

    float p3 = g00*h00+g11*h11+g22*h22+g33*h33
             + 2.f*( b01r*a01r+b01i*a01i + b02r*a02r+b02i*a02i + b03r*a03r+b03i*a03i
                   + b12r*a12r+b12i*a12i + b13r*a13r+b13i*a13i + b23r*a23r+b23i*a23i );
    float p4 = g00*g00+g11*g11+g22*g22+g33*g33
             + 2.f*( b01r*b01r+b01i*b01i + b02r*b02r+b02i*b02i + b03r*b03r+b03i*b03i
                   + b12r*b12r+b12i*b12i + b13r*b13r+b13i*b13i + b23r*b23r+b23i*b23i );

    float c1 = p1;
    float c2 = (c1*p1 - p2)*0.5f;
    float c3 = (c2*p1 - c1*p2 + p3)*(1.f/3.f);
    float c4 = (c3*p1 - c2*p2 + c1*p3 - p4)*0.25f;
    bool v = (c1 > -1e-5f) && (c2 > -1e-5f) && (c3 > -1e-5f) && (c4 > -1e-5f);

    // ---- depolarization decomposition ----
    float rn = __fdividef(1.0f, M[0] + 1e-6f);

    float D0 = M[1]*rn, D1 = M[2]*rn, D2 = M[3]*rn;
    float d   = sqrtf(D0*D0 + D1*D1 + D2*D2 + 1e-12f);
    float dcl = fminf(d, 0.9999f);
    float sq  = sqrtf(1.f - dcl*dcl);
    float dp  = d + 1e-9f;
    float rdn = __fdividef(1.f, dp);
    float Dn0 = D0*rdn, Dn1 = D1*rdn, Dn2 = D2*rdn;

    // Analytic inverse of MD via Schur complement
    float isq  = __fdividef(1.f, sq);
    float f1md = __fdividef(1.f, 1.f - dp*dp);
    float kap  = f1md - isq;
    float w0c  = dp * f1md;

    float mp[9];
#pragma unroll
    for (int i = 1; i < 4; ++i) {
        float si = M[i*4+1]*Dn0 + M[i*4+2]*Dn1 + M[i*4+3]*Dn2;
        float co = kap*si - M[i*4+0]*w0c;
        mp[(i-1)*3+0] = rn*(M[i*4+1]*isq + co*Dn0);
        mp[(i-1)*3+1] = rn*(M[i*4+2]*isq + co*Dn1);
        mp[(i-1)*3+2] = rn*(M[i*4+3]*isq + co*Dn2);
    }

    // G = mp mp^T (symmetric)
    float G00 = mp[0]*mp[0]+mp[1]*mp[1]+mp[2]*mp[2];
    float G01 = mp[0]*mp[3]+mp[1]*mp[4]+mp[2]*mp[5];
    float G02 = mp[0]*mp[6]+mp[1]*mp[7]+mp[2]*mp[8];
    float G11 = mp[3]*mp[3]+mp[4]*mp[4]+mp[5]*mp[5];
    float G12 = mp[3]*mp[6]+mp[4]*mp[7]+mp[5]*mp[8];
    float G22 = mp[6]*mp[6]+mp[7]*mp[7]+mp[8]*mp[8];

    // eigenvalues of symmetric 3x3 (trig method, same as reference)
    float qm  = (G00+G11+G22)*(1.f/3.f);
    float e00 = G00-qm, e11 = G11-qm, e22 = G22-qm;
    float pp  = sqrtf((e00*e00+e11*e11+e22*e22 + 2.f*(G01*G01+G02*G02+G12*G12))*(1.f/6.f) + 1e-20f);
    float Gq[9] = {e00,G01,G02, G01,e11,G12, G02,G12,e22};
    float r = det3v(Gq)*__fdividef(0.5f, pp*pp*pp);
    r = fminf(fmaxf(r, -1.f+1e-6f), 1.f-1e-6f);
    float phi = acosf(r)*(1.f/3.f);
    float l1 = qm + 2.f*pp*__cosf(phi);
    float l3 = qm + 2.f*pp*__cosf(phi + 2.0943951023931953f);
    float l2 = 3.f*qm - l1 - l3;
    float sg1 = sqrtf(fmaxf(l1, 1e-12f));
    float sg2 = sqrtf(fmaxf(l2, 1e-12f));
    float sg3 = sqrtf(fmaxf(l3, 1e-12f));
    float e1 = sg1+sg2+sg3;
    float e2 = sg1*sg2 + sg2*sg3 + sg3*sg1;
    float e3 = sg1*sg2*sg3;

    float sgn = (det3v(mp) >= 0.f) ? 1.f : -1.f;

    // K = G + e2' I;  mDel = sgn (e1 I + beta iK);  mR = sgn inv(Q) mp, Q = e1 I + beta iK
    float e2p = e2 + 1e-9f;
    float beta = e3 - e1*e2p;
    float K[9] = {G00+e2p, G01, G02,
                  G01, G11+e2p, G12,
                  G02, G12, G22+e2p};
    float iK[9]; inv3x3s(K, 1.f, iK);

    float dg0 = sgn*(e1 + beta*iK[0]);
    float dg1 = sgn*(e1 + beta*iK[4]);
    float dg2 = sgn*(e1 + beta*iK[8]);
    float totp = 1.f - (fabsf(dg0)+fabsf(dg1)+fabsf(dg2))*(1.f/3.f);

    float Q[9] = {e1 + beta*iK[0], beta*iK[1], beta*iK[2],
                  beta*iK[3], e1 + beta*iK[4], beta*iK[5],
                  beta*iK[6], beta*iK[7], e1 + beta*iK[8]};
    float iQ[9]; inv3x3s(Q, sgn, iQ);   // sgn folded into reciprocal

    float mR[9];
#pragma unroll
    for (int i = 0; i < 3; ++i)
#pragma unroll
        for (int j = 0; j < 3; ++j)
            mR[i*3+j] = iQ[i*3+0]*mp[0+j] + iQ[i*3+1]*mp[3+j] + iQ[i*3+2]*mp[6+j];

    float t01 = mR[0]+mR[4];
    float t10 = mR[3]-mR[1];
    float arg = sqrtf(t01*t01 + t10*t10 + 1e-12f) - 1.f;
    arg = fminf(fmaxf(arg, -1.f+1e-6f), 1.f-1e-6f);
    float linr = DEG * acosf(arg);

    float a1v = mR[5]-mR[7];
    float a2v = mR[6]-mR[2];
    bool safe = (a1v*a1v + a2v*a2v) > 1e-12f;
    float azr = atan2f(safe ? a2v : 0.f, safe ? a1v : 1.f);
    float azi = 0.5f*DEG*azr;            // in [-90, 90]
    if (azi < 0.f) azi += 180.f;         // == mod(x, 180) on this range

    if (!v) { linr = 0.f; totp = 0.f; azi = 0.f; }

    __stcs(po + 17*HW, linr);
    __stcs(po + 18*HW, totp);
    po[19*HW] = azi;                     // azi stays cached: mm_std re-reads it
}

// 8x8 box filter with reflect padding -> circular std (channel 20)
// float2-packed (cos,sin); 32x16 output tile; 2 output rows per thread.
__global__ void __launch_bounds__(256) mm_std(float* __restrict__ out, int bb) {
    __shared__ float2 t[23][40];
    __shared__ float2 h[23][33];
    int bx = blockIdx.x*32, by = blockIdx.y*16;
    int tx = threadIdx.x, ty = threadIdx.y;
    int tid = ty*32 + tx;
    const float* azi = out + ((size_t)bb*NCH_OUT + 19)*HW;

    // load 23x39 tile (reflect), converting azi -> (cos,sin) of 2*rad(azi)
    for (int i = tid; i < 23*39; i += 256) {
        int rr = i/39, cc = i - rr*39;
        int gy = by + rr - 4; if (gy < 0) gy = -gy; if (gy >= HH) gy = 2*HH-2-gy;
        int gx = bx + cc - 4; if (gx < 0) gx = -gx; if (gx >= WW) gx = 2*WW-2-gx;
        float ang = __ldg(azi + gy*WW + gx) * 0.03490658503988659f; // 2*pi/180
        float sn, cs;
        __sincosf(ang, &sn, &cs);
        t[rr][cc] = make_float2(cs, sn);
    }
    __syncthreads();

    // horizontal 8-sums
    for (int i = tid; i < 23*32; i += 256) {
        int rr = i >> 5, cc = i & 31;
        float ac = 0.f, as = 0.f;
#pragma unroll
        for (int k = 0; k < 8; ++k) {
            float2 v = t[rr][cc+k];
            ac += v.x; as += v.y;
        }
        h[rr][cc] = make_float2(ac, as);
    }
    __syncthreads();

    // vertical sums, 2 consecutive rows per thread via sliding window
    int r0 = ty*2;
    float C = 0.f, S = 0.f;
#pragma unroll
    for (int r = 0; r < 8; ++r) {
        float2 v = h[r0+r][tx];
        C += v.x; S += v.y;
    }
    size_t obase = ((size_t)bb*NCH_OUT + 20)*HW + (size_t)(by + r0)*WW + (bx+tx);
#pragma unroll
    for (int k = 0; k < 2; ++k) {
        float Cm = C*(1.f/64.f);
        float Sm = S*(1.f/64.f);
        float R = sqrtf(Cm*Cm + Sm*Sm + 1e-12f);
        R = fminf(fmaxf(R, 1e-6f), 1.f - 1e-7f);
        __stcs(out + obase + (size_t)k*WW, DEG * 0.5f * sqrtf(-2.f*__logf(R)));
        if (k < 1) {
            float2 vin = h[r0+8][tx];
            float2 vout = h[r0][tx];
            C += vin.x - vout.x;
            S += vin.y - vout.y;
        }
    }
}

extern "C" void kernel_launch(void* const* d_in, const int* in_sizes, int n_in,
                              void* d_out, int out_size) {
    const float* x = (const float*)d_in[0];
    float* out = (float*)d_out;
    int B = in_sizes[0] / (NCH_IN*HW);
    dim3 b2(32, 8);
    dim3 g2(WW/32, HH/16, 1);

    if (B >= 2 && B <= MAXB) {
        // Forked capture: mm_std(b) on g_s1 overlaps mm_main(b+1) on the main stream.
        for (int b = 0; b < B; ++b) {
            mm_main<<<HW/128, 128>>>(x, out, b);
            cudaEventRecord(g_evMain[b], 0);
            cudaStreamWaitEvent(g_s1, g_evMain[b], 0);
            mm_std<<<g2, b2, 0, g_s1>>>(out, b);
        }
        // Join forked stream back into the origin stream.
        cudaEventRecord(g_evJoin, g_s1);
        cudaStreamWaitEvent(0, g_evJoin, 0);
    } else {
        for (int b = 0; b < B; ++b) {
            mm_main<<<HW/128, 128>>>(x, out, b);
            mm_std<<<g2, b2>>>(out, b);
        }
    }
}

// round 15
// speedup vs baseline: 1.1125x; 1.1125x over previous
#include <cuda_runtime.h>
#include <math.h>

#define HH 512
#define WW 512
#define HW (HH*WW)
#define NCH_IN 48
#define NCH_OUT 21

// Adjugate (unscaled inverse) via 2x2-minor decomposition; returns det.
__device__ __forceinline__ float adj4(const float* m, float* o) {
    float s0 = m[0]*m[5]  - m[4]*m[1];
    float s1 = m[0]*m[6]  - m[4]*m[2];
    float s2 = m[0]*m[7]  - m[4]*m[3];
    float s3 = m[1]*m[6]  - m[5]*m[2];
    float s4 = m[1]*m[7]  - m[5]*m[3];
    float s5 = m[2]*m[7]  - m[6]*m[3];
    float c5 = m[10]*m[15] - m[14]*m[11];
    float c4 = m[9]*m[15]  - m[13]*m[11];
    float c3 = m[9]*m[14]  - m[13]*m[10];
    float c2 = m[8]*m[15]  - m[12]*m[11];
    float c1 = m[8]*m[14]  - m[12]*m[10];
    float c0 = m[8]*m[13]  - m[12]*m[9];
    float det = s0*c5 - s1*c4 + s2*c3 + s3*c2 - s4*c1 + s5*c0;
    o[0]  =  m[5]*c5 - m[6]*c4 + m[7]*c3;
    o[1]  = -m[1]*c5 + m[2]*c4 - m[3]*c3;
    o[2]  =  m[13]*s5 - m[14]*s4 + m[15]*s3;
    o[3]  = -m[9]*s5  + m[10]*s4 - m[11]*s3;
    o[4]  = -m[4]*c5 + m[6]*c2 - m[7]*c1;
    o[5]  =  m[0]*c5 - m[2]*c2 + m[3]*c1;
    o[6]  = -m[12]*s5 + m[14]*s2 - m[15]*s1;
    o[7]  =  m[8]*s5  - m[10]*s2 + m[11]*s1;
    o[8]  =  m[4]*c4 - m[5]*c2 + m[7]*c0;
    o[9]  = -m[0]*c4 + m[1]*c2 - m[3]*c0;
    o[10] =  m[12]*s4 - m[13]*s2 + m[15]*s0;
    o[11] = -m[8]*s4  + m[9]*s2  - m[11]*s0;
    o[12] = -m[4]*c3 + m[5]*c1 - m[6]*c0;
    o[13] =  m[0]*c3 - m[1]*c1 + m[2]*c0;
    o[14] = -m[12]*s3 + m[13]*s1 - m[14]*s0;
    o[15] =  m[8]*s3  - m[9]*s1  + m[10]*s0;
    return det;
}

__device__ __forceinline__ void mat4mul(const float* a, const float* b, float* o) {
#pragma unroll
    for (int i = 0; i < 4; ++i)
#pragma unroll
        for (int j = 0; j < 4; ++j)
            o[i*4+j] = a[i*4+0]*b[j] + a[i*4+1]*b[4+j] + a[i*4+2]*b[8+j] + a[i*4+3]*b[12+j];
}

__device__ __forceinline__ float det3v(const float g[9]) {
    return g[0]*(g[4]*g[8]-g[5]*g[7]) - g[1]*(g[3]*g[8]-g[5]*g[6]) + g[2]*(g[3]*g[7]-g[4]*g[6]);
}

// inv3x3 with caller-provided numerator (scale folded into reciprocal)
__device__ __forceinline__ void inv3x3s(const float g[9], float num, float o[9]) {
    float c00 = g[4]*g[8]-g[5]*g[7];
    float c01 = g[2]*g[7]-g[1]*g[8];
    float c02 = g[1]*g[5]-g[2]*g[4];
    float c10 = g[5]*g[6]-g[3]*g[8];
    float c11 = g[0]*g[8]-g[2]*g[6];
    float c12 = g[2]*g[3]-g[0]*g[5];
    float c20 = g[3]*g[7]-g[4]*g[6];
    float c21 = g[1]*g[6]-g[0]*g[7];
    float c22 = g[0]*g[4]-g[1]*g[3];
    float det = g[0]*c00 + g[1]*c10 + g[2]*c20;
    float rd = __fdividef(num, det);
    o[0]=c00*rd; o[1]=c01*rd; o[2]=c02*rd;
    o[3]=c10*rd; o[4]=c11*rd; o[5]=c12*rd;
    o[6]=c20*rd; o[7]=c21*rd; o[8]=c22*rd;
}

#define DEG 57.29577951308232f

__global__ void __launch_bounds__(128, 4) mm_main(const float* __restrict__ x,
                                                  float* __restrict__ out, int B) {
    int idx = blockIdx.x*blockDim.x + threadIdx.x;
    if (idx >= B*HW) return;
    int bb  = idx / HW;
    int pix = idx - bb*HW;
    const float* px = x + (size_t)bb*(NCH_IN*HW) + pix;

    // --- stage 1: A -> adjA, detA (A dies immediately) ---
    float adjA[16];
    float detA;
    {
        float Aa[16];
#pragma unroll
        for (int c = 0; c < 16; ++c) Aa[c] = __ldcs(px + (16+c)*HW);
        detA = adj4(Aa, adjA);
    }

    // --- stage 2: I -> intensity, Tm = adjA @ I (I, adjA die) ---
    float Tm[16];
    float inten = 0.f;
    {
        float Im[16];
#pragma unroll
        for (int c = 0; c < 16; ++c) Im[c] = __ldcs(px + c*HW);
#pragma unroll
        for (int c = 0; c < 16; ++c) inten += Im[c];
        inten *= (1.0f/16.0f);
        mat4mul(adjA, Im, Tm);
    }

    // --- stage 3: W -> adjW, M = (Tm @ adjW) / (detA*detW) ---
    float M[16];
    {
        float Wm[16];
#pragma unroll
        for (int c = 0; c < 16; ++c) Wm[c] = __ldcs(px + (32+c)*HW);
        float adjW[16];
        float detW = adj4(Wm, adjW);
        mat4mul(Tm, adjW, M);
        float sc = __fdividef(1.0f, detA*detW);
#pragma unroll
        for (int c = 0; c < 16; ++c) M[c] *= sc;
    }

    float* po = out + (size_t)bb*(NCH_OUT*HW) + pix;
    __stcs(po, inten);
#pragma unroll
    for (int c = 0; c < 16; ++c) __stcs(po + (1+c)*HW, M[c]);

    // ---- charpoly (physical realizability) mask via coherency matrix H ----
    const float q = 0.25f;
    float h00 = q*((M[0]+M[1]) + (M[4]+M[5]));
    float h11 = q*((M[0]-M[1]) + (M[4]-M[5]));
    float h22 = q*((M[0]+M[1]) - (M[4]+M[5]));
    float h33 = q*((M[0]-M[1]) - (M[4]-M[5]));
    float a01r = q*(M[2]+M[6]),   a01i =  q*(M[3]+M[7]);
    float a23r = q*(M[2]-M[6]),   a23i =  q*(M[3]-M[7]);
    float a02r = q*(M[8]+M[9]),   a02i = -q*(M[12]+M[13]);
    float a13r = q*(M[8]-M[9]),   a13i = -q*(M[12]-M[13]);
    float a03r = q*(M[10]+M[15]), a03i =  q*(M[11]-M[14]);
    float a12r = q*(M[10]-M[15]), a12i = -q*(M[11]+M[14]);

    float n01 = a01r*a01r + a01i*a01i;
    float n02 = a02r*a02r + a02i*a02i;
    float n03 = a03r*a03r + a03i*a03i;
    float n12 = a12r*a12r + a12i*a12i;
    float n13 = a13r*a13r + a13i*a13i;
    float n23 = a23r*a23r + a23i*a23i;

    float p1 = h00+h11+h22+h33;
    float p2 = h00*h00+h11*h11+h22*h22+h33*h33 + 2.f*(n01+n02+n03+n12+n13+n23);

    float g00 = h00*h00 + n01+n02+n03;
    float g11 = h11*h11 + n01+n12+n13;
    float g22 = h22*h22 + n02+n12+n23;
    float g33 = h33*h33 + n03+n13+n23;

    float s01 = h00+h11, s02=h00+h22, s03=h00+h33, s12=h11+h22, s13=h11+h33, s23=h22+h33;
    float b01r = s01*a01r + (a02r*a12r + a02i*a12i) + (a03r*a13r + a03i*a13i);
    float b01i = s01*a01i + (a02i*a12r - a02r*a12i) + (a03i*a13r - a03r*a13i);
    float b02r = s02*a02r + (a01r*a12r - a01i*a12i) + (a03r*a23r + a03i*a23i);
    float b02i = s02*a02i + (a01r*a12i + a01i*a12r) + (a03i*a23r - a03r*a23i);
    float b03r = s03*a03r + (a01r*a13r - a01i*a13i) + (a02r*a23r - a02i*a23i);
    float b03i = s03*a03i + (a01r*a13i + a01i*a13r) + (a02r*a23i + a02i*a23r);
    float b12r = s12*a12r + (a01r*a02r + a01i*a02i) + (a13r*a23r + a13i*a23i);
    float b12i = s12*a12i + (a01r*a02i - a01i*a02r) + (a13i*a23r - a13r*a23i);
    float b13r = s13*a13r + (a01r*a03r + a01i*a03i) + (a12r*a23r - a12i*a23i);
    float b13i = s13*a13i + (a01r*a03i - a01i*a03r) + (a12r*a23i + a12i*a23r);
    float b23r = s23*a23r + (a02r*a03r + a02i*a03i) + (a12r*a13r + a12i*a13i);
    float b23i = s23*a23i + (a02r*a03i - a02i*a03r) + (a12r*a13i - a12i*a13r);

    float p3 = g00*h00+g11*h11+g22*h22+g33*h33
             + 2.f*( b01r*a01r+b01i*a01i + b02r*a02r+b02i*a02i + b03r*a03r+b03i*a03i
                   + b12r*a12r+b12i*a12i + b13r*a13r+b13i*a13i + b23r*a23r+b23i*a23i );
    float p4 = g00*g00+g11*g11+g22*g22+g33*g33
             + 2.f*( b01r*b01r+b01i*b01i + b02r*b02r+b02i*b02i + b03r*b03r+b03i*b03i
                   + b12r*b12r+b12i*b12i + b13r*b13r+b13i*b13i + b23r*b23r+b23i*b23i );

    float c1 = p1;
    float c2 = (c1*p1 - p2)*0.5f;
    float c3 = (c2*p1 - c1*p2 + p3)*(1.f/3.f);
    float c4 = (c3*p1 - c2*p2 + c1*p3 - p4)*0.25f;
    bool v = (c1 > -1e-5f) && (c2 > -1e-5f) && (c3 > -1e-5f) && (c4 > -1e-5f);

    // ---- depolarization decomposition ----
    float rn = __fdividef(1.0f, M[0] + 1e-6f);

    float D0 = M[1]*rn, D1 = M[2]*rn, D2 = M[3]*rn;
    float d   = sqrtf(D0*D0 + D1*D1 + D2*D2 + 1e-12f);
    float dcl = fminf(d, 0.9999f);
    float sq  = sqrtf(1.f - dcl*dcl);
    float dp  = d + 1e-9f;
    float rdn = __fdividef(1.f, dp);
    float Dn0 = D0*rdn, Dn1 = D1*rdn, Dn2 = D2*rdn;

    // Analytic inverse of MD via Schur complement
    float isq  = __fdividef(1.f, sq);
    float f1md = __fdividef(1.f, 1.f - dp*dp);
    float kap  = f1md - isq;
    float w0c  = dp * f1md;

    float mp[9];
#pragma unroll
    for (int i = 1; i < 4; ++i) {
        float si = M[i*4+1]*Dn0 + M[i*4+2]*Dn1 + M[i*4+3]*Dn2;
        float co = kap*si - M[i*4+0]*w0c;
        mp[(i-1)*3+0] = rn*(M[i*4+1]*isq + co*Dn0);
        mp[(i-1)*3+1] = rn*(M[i*4+2]*isq + co*Dn1);
        mp[(i-1)*3+2] = rn*(M[i*4+3]*isq + co*Dn2);
    }

    // G = mp mp^T (symmetric)
    float G00 = mp[0]*mp[0]+mp[1]*mp[1]+mp[2]*mp[2];
    float G01 = mp[0]*mp[3]+mp[1]*mp[4]+mp[2]*mp[5];
    float G02 = mp[0]*mp[6]+mp[1]*mp[7]+mp[2]*mp[8];
    float G11 = mp[3]*mp[3]+mp[4]*mp[4]+mp[5]*mp[5];
    float G12 = mp[3]*mp[6]+mp[4]*mp[7]+mp[5]*mp[8];
    float G22 = mp[6]*mp[6]+mp[7]*mp[7]+mp[8]*mp[8];

    // eigenvalues of symmetric 3x3 (trig method, same as reference)
    float qm  = (G00+G11+G22)*(1.f/3.f);
    float e00 = G00-qm, e11 = G11-qm, e22 = G22-qm;
    float pp  = sqrtf((e00*e00+e11*e11+e22*e22 + 2.f*(G01*G01+G02*G02+G12*G12))*(1.f/6.f) + 1e-20f);
    float Gq[9] = {e00,G01,G02, G01,e11,G12, G02,G12,e22};
    float r = det3v(Gq)*__fdividef(0.5f, pp*pp*pp);
    r = fminf(fmaxf(r, -1.f+1e-6f), 1.f-1e-6f);
    float phi = acosf(r)*(1.f/3.f);
    float l1 = qm + 2.f*pp*__cosf(phi);
    float l3 = qm + 2.f*pp*__cosf(phi + 2.0943951023931953f);
    float l2 = 3.f*qm - l1 - l3;
    float sg1 = sqrtf(fmaxf(l1, 1e-12f));
    float sg2 = sqrtf(fmaxf(l2, 1e-12f));
    float sg3 = sqrtf(fmaxf(l3, 1e-12f));
    float e1 = sg1+sg2+sg3;
    float e2 = sg1*sg2 + sg2*sg3 + sg3*sg1;
    float e3 = sg1*sg2*sg3;

    float sgn = (det3v(mp) >= 0.f) ? 1.f : -1.f;

    // K = G + e2' I;  mDel = sgn (e1 I + beta iK);  mR = sgn inv(Q) mp, Q = e1 I + beta iK
    float e2p = e2 + 1e-9f;
    float beta = e3 - e1*e2p;
    float K[9] = {G00+e2p, G01, G02,
                  G01, G11+e2p, G12,
                  G02, G12, G22+e2p};
    float iK[9]; inv3x3s(K, 1.f, iK);

    float dg0 = sgn*(e1 + beta*iK[0]);
    float dg1 = sgn*(e1 + beta*iK[4]);
    float dg2 = sgn*(e1 + beta*iK[8]);
    float totp = 1.f - (fabsf(dg0)+fabsf(dg1)+fabsf(dg2))*(1.f/3.f);

    float Q[9] = {e1 + beta*iK[0], beta*iK[1], beta*iK[2],
                  beta*iK[3], e1 + beta*iK[4], beta*iK[5],
                  beta*iK[6], beta*iK[7], e1 + beta*iK[8]};
    float iQ[9]; inv3x3s(Q, sgn, iQ);   // sgn folded into reciprocal

    float mR[9];
#pragma unroll
    for (int i = 0; i < 3; ++i)
#pragma unroll
        for (int j = 0; j < 3; ++j)
            mR[i*3+j] = iQ[i*3+0]*mp[0+j] + iQ[i*3+1]*mp[3+j] + iQ[i*3+2]*mp[6+j];

    float t01 = mR[0]+mR[4];
    float t10 = mR[3]-mR[1];
    float arg = sqrtf(t01*t01 + t10*t10 + 1e-12f) - 1.f;
    arg = fminf(fmaxf(arg, -1.f+1e-6f), 1.f-1e-6f);
    float linr = DEG * acosf(arg);

    float a1v = mR[5]-mR[7];
    float a2v = mR[6]-mR[2];
    bool safe = (a1v*a1v + a2v*a2v) > 1e-12f;
    float azr = atan2f(safe ? a2v : 0.f, safe ? a1v : 1.f);
    float azi = 0.5f*DEG*azr;            // in [-90, 90]
    if (azi < 0.f) azi += 180.f;         // == mod(x, 180) on this range

    if (!v) { linr = 0.f; totp = 0.f; azi = 0.f; }

    __stcs(po + 17*HW, linr);
    __stcs(po + 18*HW, totp);
    po[19*HW] = azi;                     // azi stays cached: mm_std re-reads it
}

// 8x8 box filter with reflect padding -> circular std (channel 20)
// float2-packed (cos,sin); 32x16 output tile per 256-thread block;
// 2 output rows per thread via sliding vertical window.
__global__ void __launch_bounds__(256) mm_std(float* __restrict__ out) {
    __shared__ float2 t[23][40];
    __shared__ float2 h[23][33];
    int bx = blockIdx.x*32, by = blockIdx.y*16, bb = blockIdx.z;
    int tx = threadIdx.x, ty = threadIdx.y;
    int tid = ty*32 + tx;
    const float* azi = out + ((size_t)bb*NCH_OUT + 19)*HW;

    // load 23x39 tile (reflect), converting azi -> (cos,sin) of 2*rad(azi)
    for (int i = tid; i < 23*39; i += 256) {
        int rr = i/39, cc = i - rr*39;
        int gy = by + rr - 4; if (gy < 0) gy = -gy; if (gy >= HH) gy = 2*HH-2-gy;
        int gx = bx + cc - 4; if (gx < 0) gx = -gx; if (gx >= WW) gx = 2*WW-2-gx;
        float ang = __ldg(azi + gy*WW + gx) * 0.03490658503988659f; // 2*pi/180
        float sn, cs;
        __sincosf(ang, &sn, &cs);
        t[rr][cc] = make_float2(cs, sn);
    }
    __syncthreads();

    // horizontal 8-sums: h[r][c] = sum t[r][c..c+7]
    for (int i = tid; i < 23*32; i += 256) {
        int rr = i >> 5, cc = i & 31;
        float ac = 0.f, as = 0.f;
#pragma unroll
        for (int k = 0; k < 8; ++k) {
            float2 v = t[rr][cc+k];
            ac += v.x; as += v.y;
        }
        h[rr][cc] = make_float2(ac, as);
    }
    __syncthreads();

    // vertical sums, 2 consecutive rows per thread via sliding window
    int r0 = ty*2;
    float C = 0.f, S = 0.f;
#pragma unroll
    for (int r = 0; r < 8; ++r) {
        float2 v = h[r0+r][tx];
        C += v.x; S += v.y;
    }
    size_t obase = ((size_t)bb*NCH_OUT + 20)*HW + (size_t)(by + r0)*WW + (bx+tx);
#pragma unroll
    for (int k = 0; k < 2; ++k) {
        float Cm = C*(1.f/64.f);
        float Sm = S*(1.f/64.f);
        float R = sqrtf(Cm*Cm + Sm*Sm + 1e-12f);
        R = fminf(fmaxf(R, 1e-6f), 1.f - 1e-7f);
        __stcs(out + obase + (size_t)k*WW, DEG * 0.5f * sqrtf(-2.f*__logf(R)));
        if (k < 1) {
            float2 vin = h[r0+8][tx];
            float2 vout = h[r0][tx];
            C += vin.x - vout.x;
            S += vin.y - vout.y;
        }
    }
}

extern "C" void kernel_launch(void* const* d_in, const int* in_sizes, int n_in,
                              void* d_out, int out_size) {
    const float* x = (const float*)d_in[0];
    float* out = (float*)d_out;
    int B = in_sizes[0] / (NCH_IN*HW);
    int total = B*HW;
    mm_main<<<(total + 127)/128, 128>>>(x, out, B);
    dim3 b2(32, 8);
    dim3 g2(WW/32, HH/16, B);
    mm_std<<<g2, b2>>>(out);
}

// round 16
// speedup vs baseline: 1.1243x; 1.0106x over previous
#include <cuda_runtime.h>
#include <math.h>

#define HH 512
#define WW 512
#define HW (HH*WW)
#define NCH_IN 48
#define NCH_OUT 21

// Adjugate (unscaled inverse) via 2x2-minor decomposition; returns det.
__device__ __forceinline__ float adj4(const float* m, float* o) {
    float s0 = m[0]*m[5]  - m[4]*m[1];
    float s1 = m[0]*m[6]  - m[4]*m[2];
    float s2 = m[0]*m[7]  - m[4]*m[3];
    float s3 = m[1]*m[6]  - m[5]*m[2];
    float s4 = m[1]*m[7]  - m[5]*m[3];
    float s5 = m[2]*m[7]  - m[6]*m[3];
    float c5 = m[10]*m[15] - m[14]*m[11];
    float c4 = m[9]*m[15]  - m[13]*m[11];
    float c3 = m[9]*m[14]  - m[13]*m[10];
    float c2 = m[8]*m[15]  - m[12]*m[11];
    float c1 = m[8]*m[14]  - m[12]*m[10];
    float c0 = m[8]*m[13]  - m[12]*m[9];
    float det = s0*c5 - s1*c4 + s2*c3 + s3*c2 - s4*c1 + s5*c0;
    o[0]  =  m[5]*c5 - m[6]*c4 + m[7]*c3;
    o[1]  = -m[1]*c5 + m[2]*c4 - m[3]*c3;
    o[2]  =  m[13]*s5 - m[14]*s4 + m[15]*s3;
    o[3]  = -m[9]*s5  + m[10]*s4 - m[11]*s3;
    o[4]  = -m[4]*c5 + m[6]*c2 - m[7]*c1;
    o[5]  =  m[0]*c5 - m[2]*c2 + m[3]*c1;
    o[6]  = -m[12]*s5 + m[14]*s2 - m[15]*s1;
    o[7]  =  m[8]*s5  - m[10]*s2 + m[11]*s1;
    o[8]  =  m[4]*c4 - m[5]*c2 + m[7]*c0;
    o[9]  = -m[0]*c4 + m[1]*c2 - m[3]*c0;
    o[10] =  m[12]*s4 - m[13]*s2 + m[15]*s0;
    o[11] = -m[8]*s4  + m[9]*s2  - m[11]*s0;
    o[12] = -m[4]*c3 + m[5]*c1 - m[6]*c0;
    o[13] =  m[0]*c3 - m[1]*c1 + m[2]*c0;
    o[14] = -m[12]*s3 + m[13]*s1 - m[14]*s0;
    o[15] =  m[8]*s3  - m[9]*s1  + m[10]*s0;
    return det;
}

__device__ __forceinline__ void mat4mul(const float* a, const float* b, float* o) {
#pragma unroll
    for (int i = 0; i < 4; ++i)
#pragma unroll
        for (int j = 0; j < 4; ++j)
            o[i*4+j] = a[i*4+0]*b[j] + a[i*4+1]*b[4+j] + a[i*4+2]*b[8+j] + a[i*4+3]*b[12+j];
}

__device__ __forceinline__ float det3v(const float g[9]) {
    return g[0]*(g[4]*g[8]-g[5]*g[7]) - g[1]*(g[3]*g[8]-g[5]*g[6]) + g[2]*(g[3]*g[7]-g[4]*g[6]);
}

// inv3x3 with caller-provided numerator (scale folded into reciprocal)
__device__ __forceinline__ void inv3x3s(const float g[9], float num, float o[9]) {
    float c00 = g[4]*g[8]-g[5]*g[7];
    float c01 = g[2]*g[7]-g[1]*g[8];
    float c02 = g[1]*g[5]-g[2]*g[4];
    float c10 = g[5]*g[6]-g[3]*g[8];
    float c11 = g[0]*g[8]-g[2]*g[6];
    float c12 = g[2]*g[3]-g[0]*g[5];
    float c20 = g[3]*g[7]-g[4]*g[6];
    float c21 = g[1]*g[6]-g[0]*g[7];
    float c22 = g[0]*g[4]-g[1]*g[3];
    float det = g[0]*c00 + g[1]*c10 + g[2]*c20;
    float rd = __fdividef(num, det);
    o[0]=c00*rd; o[1]=c01*rd; o[2]=c02*rd;
    o[3]=c10*rd; o[4]=c11*rd; o[5]=c12*rd;
    o[6]=c20*rd; o[7]=c21*rd; o[8]=c22*rd;
}

#define DEG 57.29577951308232f

__global__ void __launch_bounds__(128, 4) mm_main(const float* __restrict__ x,
                                                  float* __restrict__ out, int B) {
    int idx = blockIdx.x*blockDim.x + threadIdx.x;
    if (idx >= B*HW) return;
    int bb  = idx / HW;
    int pix = idx - bb*HW;
    const float* px = x + (size_t)bb*(NCH_IN*HW) + pix;

    // --- stage 1: A -> adjA, detA (A dies immediately) ---
    float adjA[16];
    float detA;
    {
        float Aa[16];
#pragma unroll
        for (int c = 0; c < 16; ++c) Aa[c] = __ldcs(px + (16+c)*HW);
        detA = adj4(Aa, adjA);
    }

    // --- stage 2: I -> intensity, Tm = adjA @ I (I, adjA die) ---
    float Tm[16];
    float inten = 0.f;
    {
        float Im[16];
#pragma unroll
        for (int c = 0; c < 16; ++c) Im[c] = __ldcs(px + c*HW);
#pragma unroll
        for (int c = 0; c < 16; ++c) inten += Im[c];
        inten *= (1.0f/16.0f);
        mat4mul(adjA, Im, Tm);
    }

    // --- stage 3: W -> adjW, M = (Tm @ adjW) / (detA*detW) ---
    float M[16];
    {
        float Wm[16];
#pragma unroll
        for (int c = 0; c < 16; ++c) Wm[c] = __ldcs(px + (32+c)*HW);
        float adjW[16];
        float detW = adj4(Wm, adjW);
        mat4mul(Tm, adjW, M);
        float sc = __fdividef(1.0f, detA*detW);
#pragma unroll
        for (int c = 0; c < 16; ++c) M[c] *= sc;
    }

    float* po = out + (size_t)bb*(NCH_OUT*HW) + pix;
    __stcs(po, inten);
#pragma unroll
    for (int c = 0; c < 16; ++c) __stcs(po + (1+c)*HW, M[c]);

    // ---- charpoly (physical realizability) mask via coherency matrix H ----
    const float q = 0.25f;
    float h00 = q*((M[0]+M[1]) + (M[4]+M[5]));
    float h11 = q*((M[0]-M[1]) + (M[4]-M[5]));
    float h22 = q*((M[0]+M[1]) - (M[4]+M[5]));
    float h33 = q*((M[0]-M[1]) - (M[4]-M[5]));
    float a01r = q*(M[2]+M[6]),   a01i =  q*(M[3]+M[7]);
    float a23r = q*(M[2]-M[6]),   a23i =  q*(M[3]-M[7]);
    float a02r = q*(M[8]+M[9]),   a02i = -q*(M[12]+M[13]);
    float a13r = q*(M[8]-M[9]),   a13i = -q*(M[12]-M[13]);
    float a03r = q*(M[10]+M[15]), a03i =  q*(M[11]-M[14]);
    float a12r = q*(M[10]-M[15]), a12i = -q*(M[11]+M[14]);

    float n01 = a01r*a01r + a01i*a01i;
    float n02 = a02r*a02r + a02i*a02i;
    float n03 = a03r*a03r + a03i*a03i;
    float n12 = a12r*a12r + a12i*a12i;
    float n13 = a13r*a13r + a13i*a13i;
    float n23 = a23r*a23r + a23i*a23i;

    float p1 = h00+h11+h22+h33;
    float p2 = h00*h00+h11*h11+h22*h22+h33*h33 + 2.f*(n01+n02+n03+n12+n13+n23);

    float g00 = h00*h00 + n01+n02+n03;
    float g11 = h11*h11 + n01+n12+n13;
    float g22 = h22*h22 + n02+n12+n23;
    float g33 = h33*h33 + n03+n13+n23;

    float s01 = h00+h11, s02=h00+h22, s03=h00+h33, s12=h11+h22, s13=h11+h33, s23=h22+h33;
    float b01r = s01*a01r + (a02r*a12r + a02i*a12i) + (a03r*a13r + a03i*a13i);
    float b01i = s01*a01i + (a02i*a12r - a02r*a12i) + (a03i*a13r - a03r*a13i);
    float b02r = s02*a02r + (a01r*a12r - a01i*a12i) + (a03r*a23r + a03i*a23i);
    float b02i = s02*a02i + (a01r*a12i + a01i*a12r) + (a03i*a23r - a03r*a23i);
    float b03r = s03*a03r + (a01r*a13r - a01i*a13i) + (a02r*a23r - a02i*a23i);
    float b03i = s03*a03i + (a01r*a13i + a01i*a13r) + (a02r*a23i + a02i*a23r);
    float b12r = s12*a12r + (a01r*a02r + a01i*a02i) + (a13r*a23r + a13i*a23i);
    float b12i = s12*a12i + (a01r*a02i - a01i*a02r) + (a13i*a23r - a13r*a23i);
    float b13r = s13*a13r + (a01r*a03r + a01i*a03i) + (a12r*a23r - a12i*a23i);
    float b13i = s13*a13i + (a01r*a03i - a01i*a03r) + (a12r*a23i + a12i*a23r);
    float b23r = s23*a23r + (a02r*a03r + a02i*a03i) + (a12r*a13r + a12i*a13i);
    float b23i = s23*a23i + (a02r*a03i - a02i*a03r) + (a12r*a13i - a12i*a13r);

    float p3 = g00*h00+g11*h11+g22*h22+g33*h33
             + 2.f*( b01r*a01r+b01i*a01i + b02r*a02r+b02i*a02i + b03r*a03r+b03i*a03i
                   + b12r*a12r+b12i*a12i + b13r*a13r+b13i*a13i + b23r*a23r+b23i*a23i );
    float p4 = g00*g00+g11*g11+g22*g22+g33*g33
             + 2.f*( b01r*b01r+b01i*b01i + b02r*b02r+b02i*b02i + b03r*b03r+b03i*b03i
                   + b12r*b12r+b12i*b12i + b13r*b13r+b13i*b13i + b23r*b23r+b23i*b23i );

    float c1 = p1;
    float c2 = (c1*p1 - p2)*0.5f;
    float c3 = (c2*p1 - c1*p2 + p3)*(1.f/3.f);
    float c4 = (c3*p1 - c2*p2 + c1*p3 - p4)*0.25f;
    bool v = (c1 > -1e-5f) && (c2 > -1e-5f) && (c3 > -1e-5f) && (c4 > -1e-5f);

    // ---- depolarization decomposition ----
    float rn = __fdividef(1.0f, M[0] + 1e-6f);

    float D0 = M[1]*rn, D1 = M[2]*rn, D2 = M[3]*rn;
    float d   = sqrtf(D0*D0 + D1*D1 + D2*D2 + 1e-12f);
    float dcl = fminf(d, 0.9999f);
    float sq  = sqrtf(1.f - dcl*dcl);
    float dp  = d + 1e-9f;
    float rdn = __fdividef(1.f, dp);
    float Dn0 = D0*rdn, Dn1 = D1*rdn, Dn2 = D2*rdn;

    // Analytic inverse of MD via Schur complement
    float isq  = __fdividef(1.f, sq);
    float f1md = __fdividef(1.f, 1.f - dp*dp);
    float kap  = f1md - isq;
    float w0c  = dp * f1md;

    float mp[9];
#pragma unroll
    for (int i = 1; i < 4; ++i) {
        float si = M[i*4+1]*Dn0 + M[i*4+2]*Dn1 + M[i*4+3]*Dn2;
        float co = kap*si - M[i*4+0]*w0c;
        mp[(i-1)*3+0] = rn*(M[i*4+1]*isq + co*Dn0);
        mp[(i-1)*3+1] = rn*(M[i*4+2]*isq + co*Dn1);
        mp[(i-1)*3+2] = rn*(M[i*4+3]*isq + co*Dn2);
    }

    // G = mp mp^T (symmetric)
    float G00 = mp[0]*mp[0]+mp[1]*mp[1]+mp[2]*mp[2];
    float G01 = mp[0]*mp[3]+mp[1]*mp[4]+mp[2]*mp[5];
    float G02 = mp[0]*mp[6]+mp[1]*mp[7]+mp[2]*mp[8];
    float G11 = mp[3]*mp[3]+mp[4]*mp[4]+mp[5]*mp[5];
    float G12 = mp[3]*mp[6]+mp[4]*mp[7]+mp[5]*mp[8];
    float G22 = mp[6]*mp[6]+mp[7]*mp[7]+mp[8]*mp[8];

    // eigenvalues of symmetric 3x3 (trig method, same as reference)
    float qm  = (G00+G11+G22)*(1.f/3.f);
    float e00 = G00-qm, e11 = G11-qm, e22 = G22-qm;
    float pp  = sqrtf((e00*e00+e11*e11+e22*e22 + 2.f*(G01*G01+G02*G02+G12*G12))*(1.f/6.f) + 1e-20f);
    float Gq[9] = {e00,G01,G02, G01,e11,G12, G02,G12,e22};
    float r = det3v(Gq)*__fdividef(0.5f, pp*pp*pp);
    r = fminf(fmaxf(r, -1.f+1e-6f), 1.f-1e-6f);
    float phi = acosf(r)*(1.f/3.f);
    float l1 = qm + 2.f*pp*__cosf(phi);
    float l3 = qm + 2.f*pp*__cosf(phi + 2.0943951023931953f);
    float l2 = 3.f*qm - l1 - l3;
    float sg1 = sqrtf(fmaxf(l1, 1e-12f));
    float sg2 = sqrtf(fmaxf(l2, 1e-12f));
    float sg3 = sqrtf(fmaxf(l3, 1e-12f));
    float e1 = sg1+sg2+sg3;
    float e2 = sg1*sg2 + sg2*sg3 + sg3*sg1;
    float e3 = sg1*sg2*sg3;

    float sgn = (det3v(mp) >= 0.f) ? 1.f : -1.f;

    // K = G + e2' I;  mDel = sgn (e1 I + beta iK);  mR = sgn inv(Q) mp, Q = e1 I + beta iK
    float e2p = e2 + 1e-9f;
    float beta = e3 - e1*e2p;
    float K[9] = {G00+e2p, G01, G02,
                  G01, G11+e2p, G12,
                  G02, G12, G22+e2p};
    float iK[9]; inv3x3s(K, 1.f, iK);

    float dg0 = sgn*(e1 + beta*iK[0]);
    float dg1 = sgn*(e1 + beta*iK[4]);
    float dg2 = sgn*(e1 + beta*iK[8]);
    float totp = 1.f - (fabsf(dg0)+fabsf(dg1)+fabsf(dg2))*(1.f/3.f);

    float Q[9] = {e1 + beta*iK[0], beta*iK[1], beta*iK[2],
                  beta*iK[3], e1 + beta*iK[4], beta*iK[5],
                  beta*iK[6], beta*iK[7], e1 + beta*iK[8]};
    float iQ[9]; inv3x3s(Q, sgn, iQ);   // sgn folded into reciprocal

    float mR[9];
#pragma unroll
    for (int i = 0; i < 3; ++i)
#pragma unroll
        for (int j = 0; j < 3; ++j)
            mR[i*3+j] = iQ[i*3+0]*mp[0+j] + iQ[i*3+1]*mp[3+j] + iQ[i*3+2]*mp[6+j];

    float t01 = mR[0]+mR[4];
    float t10 = mR[3]-mR[1];
    float arg = sqrtf(t01*t01 + t10*t10 + 1e-12f) - 1.f;
    arg = fminf(fmaxf(arg, -1.f+1e-6f), 1.f-1e-6f);
    float linr = DEG * acosf(arg);

    float a1v = mR[5]-mR[7];
    float a2v = mR[6]-mR[2];
    bool safe = (a1v*a1v + a2v*a2v) > 1e-12f;
    float azr = atan2f(safe ? a2v : 0.f, safe ? a1v : 1.f);
    float azi = 0.5f*DEG*azr;            // in [-90, 90]
    if (azi < 0.f) azi += 180.f;         // == mod(x, 180) on this range

    if (!v) { linr = 0.f; totp = 0.f; azi = 0.f; }

    __stcs(po + 17*HW, linr);
    __stcs(po + 18*HW, totp);
    po[19*HW] = azi;                     // azi stays cached: mm_std re-reads it
}

// 8x8 box filter with reflect padding -> circular std (channel 20)
// float2-packed; division-free row-based load with interior fast path;
// two-level horizontal sums (4-sums then pairs); 32x16 tile, 2 rows/thread.
__global__ void __launch_bounds__(256) mm_std(float* __restrict__ out) {
    __shared__ float2 t[23][40];
    __shared__ float2 h4[23][36];
    __shared__ float2 h[23][33];
    int bx = blockIdx.x*32, by = blockIdx.y*16, bb = blockIdx.z;
    int tx = threadIdx.x, ty = threadIdx.y;
    int tid = ty*32 + tx;
    const float* azi = out + ((size_t)bb*NCH_OUT + 19)*HW;
    const float KANG = 0.03490658503988659f; // 2*pi/180

    // load 23x39 tile -> (cos,sin) of 2*rad(azi)
    bool interior = (bx >= 4) && (bx + 35 <= WW) && (by >= 4) && (by + 19 <= HH);
    if (interior) {
        const float* base = azi + (size_t)(by - 4)*WW + (bx - 4);
        for (int r = ty; r < 23; r += 8) {
            const float* rowp = base + r*WW;
            for (int c = tx; c < 39; c += 32) {
                float ang = __ldg(rowp + c) * KANG;
                float sn, cs;
                __sincosf(ang, &sn, &cs);
                t[r][c] = make_float2(cs, sn);
            }
        }
    } else {
        for (int r = ty; r < 23; r += 8) {
            int gy = by + r - 4; if (gy < 0) gy = -gy; if (gy >= HH) gy = 2*HH-2-gy;
            const float* rowp = azi + (size_t)gy*WW;
            for (int c = tx; c < 39; c += 32) {
                int gx = bx + c - 4; if (gx < 0) gx = -gx; if (gx >= WW) gx = 2*WW-2-gx;
                float ang = __ldg(rowp + gx) * KANG;
                float sn, cs;
                __sincosf(ang, &sn, &cs);
                t[r][c] = make_float2(cs, sn);
            }
        }
    }
    __syncthreads();

    // horizontal 4-sums: h4[r][c] = sum t[r][c..c+3], 23*36 values
    for (int i = tid; i < 23*36; i += 256) {
        int rr = i/36, cc = i - rr*36;
        float2 a = t[rr][cc], b = t[rr][cc+1], c = t[rr][cc+2], d = t[rr][cc+3];
        h4[rr][cc] = make_float2((a.x+b.x)+(c.x+d.x), (a.y+b.y)+(c.y+d.y));
    }
    __syncthreads();

    // horizontal 8-sums from pairs of 4-sums: h[r][c] = h4[r][c] + h4[r][c+4]
    for (int i = tid; i < 23*32; i += 256) {
        int rr = i >> 5, cc = i & 31;
        float2 a = h4[rr][cc], b = h4[rr][cc+4];
        h[rr][cc] = make_float2(a.x+b.x, a.y+b.y);
    }
    __syncthreads();

    // vertical sums, 2 consecutive rows per thread via sliding window
    int r0 = ty*2;
    float C = 0.f, S = 0.f;
#pragma unroll
    for (int r = 0; r < 8; ++r) {
        float2 v = h[r0+r][tx];
        C += v.x; S += v.y;
    }
    size_t obase = ((size_t)bb*NCH_OUT + 20)*HW + (size_t)(by + r0)*WW + (bx+tx);
#pragma unroll
    for (int k = 0; k < 2; ++k) {
        float Cm = C*(1.f/64.f);
        float Sm = S*(1.f/64.f);
        float R = sqrtf(Cm*Cm + Sm*Sm + 1e-12f);
        R = fminf(fmaxf(R, 1e-6f), 1.f - 1e-7f);
        __stcs(out + obase + (size_t)k*WW, DEG * 0.5f * sqrtf(-2.f*__logf(R)));
        if (k < 1) {
            float2 vin = h[r0+8][tx];
            float2 vout = h[r0][tx];
            C += vin.x - vout.x;
            S += vin.y - vout.y;
        }
    }
}

extern "C" void kernel_launch(void* const* d_in, const int* in_sizes, int n_in,
                              void* d_out, int out_size) {
    const float* x = (const float*)d_in[0];
    float* out = (float*)d_out;
    int B = in_sizes[0] / (NCH_IN*HW);
    int total = B*HW;
    mm_main<<<(total + 127)/128, 128>>>(x, out, B);
    dim3 b2(32, 8);
    dim3 g2(WW/32, HH/16, B);
    mm_std<<<g2, b2>>>(out);
}